// round 15
// baseline (speedup 1.0000x reference)
#include <cuda_runtime.h>
#include <cuda_bf16.h>
#include <cstdint>

// Problem dims
#define BB 8
#define SS 1024          // IMG*IMG
#define EE 768           // D_EMBED == D_MODEL
#define NH 12
#define DD 64
#define EW 384           // EE/2 packed words per row

// ---------------- scratch (device globals; no allocs allowed) ----------------
__device__ float g_q[BB * SS * EE];
__device__ float g_k[BB * SS * EE];
__device__ float g_v[BB * SS * EE];
__device__ float g_ctx[BB * SS * EE];
// presplit planes: X^T pairs along c: [t][c/2][s]; W pairs along c: [mat][o][c/2]
__device__ uint32_t g_xh[3 * BB * EW * SS];
__device__ uint32_t g_xl[3 * BB * EW * SS];
__device__ uint32_t g_wh[4 * EE * EW];
__device__ uint32_t g_wl[4 * EE * EW];

// =============================================================================
// bf16 split helpers: x = hi + lo, both bf16. Packed pairs along k.
// =============================================================================
__device__ __forceinline__ void split2_bf16(float x0, float x1,
                                            uint32_t& hw, uint32_t& lw) {
    __nv_bfloat162 h = __floats2bfloat162_rn(x0, x1);
    float2 hf = __bfloat1622float2(h);
    __nv_bfloat162 l = __floats2bfloat162_rn(x0 - hf.x, x1 - hf.y);
    hw = *reinterpret_cast<uint32_t*>(&h);
    lw = *reinterpret_cast<uint32_t*>(&l);
}

__device__ __forceinline__ void mma_bf16(float* d, const uint32_t* a, const uint32_t* b) {
    asm volatile(
        "mma.sync.aligned.m16n8k16.row.col.f32.bf16.bf16.f32 "
        "{%0,%1,%2,%3}, {%4,%5,%6,%7}, {%8,%9}, {%0,%1,%2,%3};"
        : "+f"(d[0]), "+f"(d[1]), "+f"(d[2]), "+f"(d[3])
        : "r"(a[0]), "r"(a[1]), "r"(a[2]), "r"(a[3]),
          "r"(b[0]), "r"(b[1]));
}

// Three interleaved passes over all 8 (mt,nt) accumulators (R13).
#define MMA_PASSES(acc, ah, al, bhv, blv)                                   \
    do {                                                                    \
        _Pragma("unroll")                                                   \
        for (int nt_ = 0; nt_ < 4; nt_++) {                                 \
            _Pragma("unroll")                                               \
            for (int mt_ = 0; mt_ < 2; mt_++)                               \
                mma_bf16(acc[mt_][nt_], ah[mt_], bhv[nt_]);                 \
        }                                                                   \
        _Pragma("unroll")                                                   \
        for (int nt_ = 0; nt_ < 4; nt_++) {                                 \
            _Pragma("unroll")                                               \
            for (int mt_ = 0; mt_ < 2; mt_++)                               \
                mma_bf16(acc[mt_][nt_], ah[mt_], blv[nt_]);                 \
        }                                                                   \
        _Pragma("unroll")                                                   \
        for (int nt_ = 0; nt_ < 4; nt_++) {                                 \
            _Pragma("unroll")                                               \
            for (int mt_ = 0; mt_ < 2; mt_++)                               \
                mma_bf16(acc[mt_][nt_], al[mt_], bhv[nt_]);                 \
        }                                                                   \
    } while (0)

// =============================================================================
// Kernel 0a: presplit X into c-pair planes (pairing matches R13 proj staging).
// =============================================================================
__global__ __launch_bounds__(256) void presplit_x_kernel(
    const float* __restrict__ xq, const float* __restrict__ xk, const float* __restrict__ xv)
{
    size_t wb = ((size_t)blockIdx.x * 256 + threadIdx.x) * 4;
    int t   = (int)(wb / ((size_t)EW * SS));
    int rem = (int)(wb % ((size_t)EW * SS));
    int j = rem >> 10;            // c-pair index
    int s = rem & 1023;           // column (multiple of 4)

    const float* x = (t < 8) ? xq : (t < 16) ? xk : xv;
    int b = t & 7;
    const float* r0 = x + ((size_t)b * EE + 2 * j) * SS + s;
    float4 a = *(const float4*)r0;
    float4 c = *(const float4*)(r0 + SS);
    uint4 hv, lv;
    split2_bf16(a.x, c.x, hv.x, lv.x);
    split2_bf16(a.y, c.y, hv.y, lv.y);
    split2_bf16(a.z, c.z, hv.z, lv.z);
    split2_bf16(a.w, c.w, hv.w, lv.w);
    *(uint4*)(g_xh + wb) = hv;
    *(uint4*)(g_xl + wb) = lv;
}

// =============================================================================
// Kernel 0b: presplit weights (wq,wk,wv,fcw) into c-pair planes.
// =============================================================================
__global__ __launch_bounds__(256) void presplit_w_kernel(
    const float* __restrict__ wq, const float* __restrict__ wk,
    const float* __restrict__ wv, const float* __restrict__ fw)
{
    size_t wb = ((size_t)blockIdx.x * 256 + threadIdx.x) * 4;
    int mat = (int)(wb / (EE * EW));
    int rem = (int)(wb % (EE * EW));
    const float* w = (mat == 0) ? wq : (mat == 1) ? wk : (mat == 2) ? wv : fw;
    int o  = rem / EW;
    int jw = rem % EW;
    const float* src = w + (size_t)o * EE + 2 * jw;
    float4 e0 = *(const float4*)src;
    float4 e1 = *(const float4*)(src + 4);
    uint4 hv, lv;
    split2_bf16(e0.x, e0.y, hv.x, lv.x);
    split2_bf16(e0.z, e0.w, hv.y, lv.y);
    split2_bf16(e1.x, e1.y, hv.z, lv.z);
    split2_bf16(e1.z, e1.w, hv.w, lv.w);
    *(uint4*)(g_wh + wb) = hv;
    *(uint4*)(g_wl + wb) = lv;
}

// =============================================================================
// Kernel 1: QKV projection (R13 mainloop/epilogue; copy-only staging).
// =============================================================================
#define GP_AP 136
#define GP_BP 20
#define GP_AHo 0
#define GP_ALo 2176
#define GP_BHo 4352
#define GP_BLo 5632
#define GP_SMEM_WORDS 6912
#define GP_SMEM_BYTES (GP_SMEM_WORDS * 4)

__global__ __launch_bounds__(256) void proj_mma_kernel(
    const float* __restrict__ bq, const float* __restrict__ bk, const float* __restrict__ bv)
{
    extern __shared__ uint32_t su[];
    uint32_t* AH = su + GP_AHo;
    uint32_t* AL = su + GP_ALo;
    uint32_t* BH = su + GP_BHo;
    uint32_t* BL = su + GP_BLo;

    const int mat = blockIdx.z >> 3;
    const int b   = blockIdx.z & 7;
    const int t   = mat * 8 + b;

    const float* bi = (mat == 0) ? bq : (mat == 1) ? bk : bv;
    float* y = ((mat == 0) ? g_q : (mat == 1) ? g_k : g_v) + (size_t)b * SS * EE;

    const uint32_t* xh = g_xh + (size_t)t * EW * SS;
    const uint32_t* xl = g_xl + (size_t)t * EW * SS;
    const uint32_t* wh = g_wh + (size_t)mat * EE * EW;
    const uint32_t* wl = g_wl + (size_t)mat * EE * EW;

    const int m0 = blockIdx.x * 128;
    const int n0 = blockIdx.y * 64;

    const int tid  = threadIdx.x;
    const int lane = tid & 31;
    const int w8   = tid >> 5;
    const int wm   = w8 >> 1;
    const int wn   = w8 & 1;
    const int gid  = lane >> 2;
    const int ctid = lane & 3;

    float acc[2][4][4];
    #pragma unroll
    for (int i = 0; i < 2; i++)
        #pragma unroll
        for (int j = 0; j < 4; j++)
            #pragma unroll
            for (int q = 0; q < 4; q++) acc[i][j][q] = 0.f;

    for (int kg2 = 0; kg2 < EW; kg2 += 16) {     // 16 k-pairs per chunk
        __syncthreads();
        // stage A: pure copy from X planes [kw][m]
        #pragma unroll
        for (int p = 0; p < 2; p++) {
            int idx = tid + p * 256;
            int j   = idx >> 5;
            int m4  = (idx & 31) << 2;
            size_t src = (size_t)(kg2 + j) * SS + m0 + m4;
            *(uint4*)(AH + j * GP_AP + m4) = *(const uint4*)(xh + src);
            *(uint4*)(AL + j * GP_AP + m4) = *(const uint4*)(xl + src);
        }
        // stage B: pure copy from W planes [n][kw]
        {
            int r  = tid >> 2;
            int w4 = (tid & 3) << 2;
            size_t src = (size_t)(n0 + r) * EW + kg2 + w4;
            *(uint4*)(BH + r * GP_BP + w4) = *(const uint4*)(wh + src);
            *(uint4*)(BL + r * GP_BP + w4) = *(const uint4*)(wl + src);
        }
        __syncthreads();

        #pragma unroll
        for (int kwb = 0; kwb < 16; kwb += 8) {
            uint32_t ah[2][4], al[2][4];
            #pragma unroll
            for (int mt = 0; mt < 2; mt++) {
                int mrow = wm * 32 + mt * 16 + gid;
                const uint32_t* ph = AH + (kwb + ctid) * GP_AP + mrow;
                const uint32_t* pl = AL + (kwb + ctid) * GP_AP + mrow;
                ah[mt][0] = ph[0];          ah[mt][1] = ph[8];
                ah[mt][2] = ph[4*GP_AP];    ah[mt][3] = ph[4*GP_AP + 8];
                al[mt][0] = pl[0];          al[mt][1] = pl[8];
                al[mt][2] = pl[4*GP_AP];    al[mt][3] = pl[4*GP_AP + 8];
            }
            uint32_t bhv[4][2], blv[4][2];
            #pragma unroll
            for (int nt = 0; nt < 4; nt++) {
                int nrow = wn * 32 + nt * 8 + gid;
                const uint32_t* pbh = BH + nrow * GP_BP + kwb + ctid;
                const uint32_t* pbl = BL + nrow * GP_BP + kwb + ctid;
                bhv[nt][0] = pbh[0]; bhv[nt][1] = pbh[4];
                blv[nt][0] = pbl[0]; blv[nt][1] = pbl[4];
            }
            MMA_PASSES(acc, ah, al, bhv, blv);
        }
    }

    #pragma unroll
    for (int nt = 0; nt < 4; nt++) {
        int col = n0 + wn * 32 + nt * 8 + 2 * ctid;
        float b0 = bi[col], b1 = bi[col + 1];
        #pragma unroll
        for (int mt = 0; mt < 2; mt++) {
            int row = m0 + wm * 32 + mt * 16 + gid;
            *(float2*)(y + (size_t)row * EE + col) =
                make_float2(acc[mt][nt][0] + b0, acc[mt][nt][1] + b1);
            *(float2*)(y + (size_t)(row + 8) * EE + col) =
                make_float2(acc[mt][nt][2] + b0, acc[mt][nt][3] + b1);
        }
    }
}

// =============================================================================
// Kernel 2a: scores GEMM (R13, unchanged).
// =============================================================================
#define SK_P 36
#define SK_AHo 0
#define SK_ALo 4608
#define SK_BHo 9216
#define SK_BLo 11520
#define SK_SMEM_WORDS 13824
#define SK_SMEM_BYTES (SK_SMEM_WORDS * 4)

__global__ __launch_bounds__(256) void scores_mma_kernel(float* __restrict__ probs)
{
    extern __shared__ uint32_t su[];
    uint32_t* AH = su + SK_AHo;
    uint32_t* AL = su + SK_ALo;
    uint32_t* BH = su + SK_BHo;
    uint32_t* BL = su + SK_BLo;

    const int bh = blockIdx.z;
    const int b  = bh / NH;
    const int h  = bh % NH;
    const int m0 = blockIdx.x * 128;
    const int n0 = blockIdx.y * 64;

    const float* qp = g_q + ((size_t)b * SS) * EE + h * DD;
    const float* kp = g_k + ((size_t)b * SS) * EE + h * DD;

    const int tid  = threadIdx.x;
    const int lane = tid & 31;
    const int w8   = tid >> 5;
    const int wm   = w8 >> 1;
    const int wn   = w8 & 1;
    const int gid  = lane >> 2;
    const int ctid = lane & 3;

    #pragma unroll
    for (int p = 0; p < 4; p++) {
        int idx = tid + p * 256;
        int r   = idx >> 3;
        int kq  = (idx & 7) << 3;
        const float* qr = qp + (size_t)(m0 + r) * EE + kq;
        float4 a0 = *(const float4*)qr;
        float4 a1 = *(const float4*)(qr + 4);
        uint4 hv, lv;
        split2_bf16(a0.x, a0.y, hv.x, lv.x);
        split2_bf16(a0.z, a0.w, hv.y, lv.y);
        split2_bf16(a1.x, a1.y, hv.z, lv.z);
        split2_bf16(a1.z, a1.w, hv.w, lv.w);
        *(uint4*)(AH + r * SK_P + (idx & 7) * 4) = hv;
        *(uint4*)(AL + r * SK_P + (idx & 7) * 4) = lv;
    }
    #pragma unroll
    for (int p = 0; p < 2; p++) {
        int idx = tid + p * 256;
        int r   = idx >> 3;
        int kq  = (idx & 7) << 3;
        const float* kr = kp + (size_t)(n0 + r) * EE + kq;
        float4 b0 = *(const float4*)kr;
        float4 b1 = *(const float4*)(kr + 4);
        uint4 hv, lv;
        split2_bf16(b0.x, b0.y, hv.x, lv.x);
        split2_bf16(b0.z, b0.w, hv.y, lv.y);
        split2_bf16(b1.x, b1.y, hv.z, lv.z);
        split2_bf16(b1.z, b1.w, hv.w, lv.w);
        *(uint4*)(BH + r * SK_P + (idx & 7) * 4) = hv;
        *(uint4*)(BL + r * SK_P + (idx & 7) * 4) = lv;
    }
    __syncthreads();

    float acc[2][4][4];
    #pragma unroll
    for (int i = 0; i < 2; i++)
        #pragma unroll
        for (int j = 0; j < 4; j++)
            #pragma unroll
            for (int q = 0; q < 4; q++) acc[i][j][q] = 0.f;

    #pragma unroll
    for (int kwb = 0; kwb < 32; kwb += 8) {
        uint32_t ah[2][4], al[2][4];
        #pragma unroll
        for (int mt = 0; mt < 2; mt++) {
            int mrow = wm * 32 + mt * 16 + gid;
            const uint32_t* ph = AH + mrow * SK_P + kwb + ctid;
            const uint32_t* pl = AL + mrow * SK_P + kwb + ctid;
            ah[mt][0] = ph[0];          ah[mt][1] = ph[8*SK_P];
            ah[mt][2] = ph[4];          ah[mt][3] = ph[8*SK_P + 4];
            al[mt][0] = pl[0];          al[mt][1] = pl[8*SK_P];
            al[mt][2] = pl[4];          al[mt][3] = pl[8*SK_P + 4];
        }
        uint32_t bhv[4][2], blv[4][2];
        #pragma unroll
        for (int nt = 0; nt < 4; nt++) {
            int nrow = wn * 32 + nt * 8 + gid;
            const uint32_t* pbh = BH + nrow * SK_P + kwb + ctid;
            const uint32_t* pbl = BL + nrow * SK_P + kwb + ctid;
            bhv[nt][0] = pbh[0]; bhv[nt][1] = pbh[4];
            blv[nt][0] = pbl[0]; blv[nt][1] = pbl[4];
        }
        MMA_PASSES(acc, ah, al, bhv, blv);
    }

    float* pbase = probs + (size_t)bh * SS * SS;
    #pragma unroll
    for (int mt = 0; mt < 2; mt++)
        #pragma unroll
        for (int nt = 0; nt < 4; nt++) {
            int row = m0 + wm * 32 + mt * 16 + gid;
            int col = n0 + wn * 32 + nt * 8 + 2 * ctid;
            *(float2*)(pbase + (size_t)row * SS + col) =
                make_float2(acc[mt][nt][0] * 0.125f, acc[mt][nt][1] * 0.125f);
            *(float2*)(pbase + (size_t)(row + 8) * SS + col) =
                make_float2(acc[mt][nt][2] * 0.125f, acc[mt][nt][3] * 0.125f);
        }
}

// =============================================================================
// Kernel 2b: in-place row softmax (R13, unchanged).
// =============================================================================
__global__ __launch_bounds__(256) void softmax_kernel(float* __restrict__ probs)
{
    const int warp = threadIdx.x >> 5;
    const int lane = threadIdx.x & 31;
    const size_t row = (size_t)blockIdx.x * 8 + warp;

    float4* rp = (float4*)(probs + row * SS);

    float4 v[8];
    #pragma unroll
    for (int i = 0; i < 8; i++) v[i] = rp[lane + 32 * i];

    float mx = -3.4e38f;
    #pragma unroll
    for (int i = 0; i < 8; i++)
        mx = fmaxf(mx, fmaxf(fmaxf(v[i].x, v[i].y), fmaxf(v[i].z, v[i].w)));
    #pragma unroll
    for (int o = 16; o > 0; o >>= 1)
        mx = fmaxf(mx, __shfl_xor_sync(0xFFFFFFFFu, mx, o));

    float sum = 0.f;
    #pragma unroll
    for (int i = 0; i < 8; i++) {
        v[i].x = __expf(v[i].x - mx);
        v[i].y = __expf(v[i].y - mx);
        v[i].z = __expf(v[i].z - mx);
        v[i].w = __expf(v[i].w - mx);
        sum += v[i].x + v[i].y + v[i].z + v[i].w;
    }
    #pragma unroll
    for (int o = 16; o > 0; o >>= 1)
        sum += __shfl_xor_sync(0xFFFFFFFFu, sum, o);

    float inv = 1.f / sum;
    #pragma unroll
    for (int i = 0; i < 8; i++) {
        v[i].x *= inv; v[i].y *= inv; v[i].z *= inv; v[i].w *= inv;
        rp[lane + 32 * i] = v[i];
    }
}

// =============================================================================
// Kernel 2c: ctx GEMM (R13, unchanged).
// =============================================================================
#define CX_AP 20
#define CX_BP 72
#define CX_AHo 0
#define CX_ALo 2560
#define CX_BHo 5120
#define CX_BLo 6272
#define CX_SMEM_WORDS 7424
#define CX_SMEM_BYTES (CX_SMEM_WORDS * 4)

__global__ __launch_bounds__(256) void ctx_mma_kernel(const float* __restrict__ probs)
{
    extern __shared__ uint32_t su[];
    uint32_t* AH = su + CX_AHo;
    uint32_t* AL = su + CX_ALo;
    uint32_t* BH = su + CX_BHo;
    uint32_t* BL = su + CX_BLo;

    const int bh = blockIdx.z;
    const int b  = bh / NH;
    const int h  = bh % NH;
    const int m0 = blockIdx.x * 128;

    const float* pb = probs + (size_t)bh * SS * SS;
    const float* vb = g_v + ((size_t)b * SS) * EE + h * DD;

    const int tid  = threadIdx.x;
    const int lane = tid & 31;
    const int w8   = tid >> 5;
    const int wm   = w8 >> 1;
    const int wn   = w8 & 1;
    const int gid  = lane >> 2;
    const int ctid = lane & 3;

    float acc[2][4][4];
    #pragma unroll
    for (int i = 0; i < 2; i++)
        #pragma unroll
        for (int j = 0; j < 4; j++)
            #pragma unroll
            for (int q = 0; q < 4; q++) acc[i][j][q] = 0.f;

    for (int kg = 0; kg < SS; kg += 32) {
        __syncthreads();
        #pragma unroll
        for (int p = 0; p < 2; p++) {
            int idx = tid + p * 256;
            int r   = idx >> 2;
            int kq  = (idx & 3) << 3;
            const float* pr = pb + (size_t)(m0 + r) * SS + kg + kq;
            float4 a0 = *(const float4*)pr;
            float4 a1 = *(const float4*)(pr + 4);
            uint4 hv, lv;
            split2_bf16(a0.x, a0.y, hv.x, lv.x);
            split2_bf16(a0.z, a0.w, hv.y, lv.y);
            split2_bf16(a1.x, a1.y, hv.z, lv.z);
            split2_bf16(a1.z, a1.w, hv.w, lv.w);
            *(uint4*)(AH + r * CX_AP + (idx & 3) * 4) = hv;
            *(uint4*)(AL + r * CX_AP + (idx & 3) * 4) = lv;
        }
        {
            int j  = tid >> 4;
            int d4 = (tid & 15) << 2;
            const float* vr = vb + (size_t)(kg + 2 * j) * EE + d4;
            float4 r0 = *(const float4*)vr;
            float4 r1 = *(const float4*)(vr + EE);
            uint4 hv, lv;
            split2_bf16(r0.x, r1.x, hv.x, lv.x);
            split2_bf16(r0.y, r1.y, hv.y, lv.y);
            split2_bf16(r0.z, r1.z, hv.z, lv.z);
            split2_bf16(r0.w, r1.w, hv.w, lv.w);
            *(uint4*)(BH + j * CX_BP + d4) = hv;
            *(uint4*)(BL + j * CX_BP + d4) = lv;
        }
        __syncthreads();

        #pragma unroll
        for (int kwb = 0; kwb < 16; kwb += 8) {
            uint32_t ah[2][4], al[2][4];
            #pragma unroll
            for (int mt = 0; mt < 2; mt++) {
                int mrow = wm * 32 + mt * 16 + gid;
                const uint32_t* ph = AH + mrow * CX_AP + kwb + ctid;
                const uint32_t* pl = AL + mrow * CX_AP + kwb + ctid;
                ah[mt][0] = ph[0];          ah[mt][1] = ph[8*CX_AP];
                ah[mt][2] = ph[4];          ah[mt][3] = ph[8*CX_AP + 4];
                al[mt][0] = pl[0];          al[mt][1] = pl[8*CX_AP];
                al[mt][2] = pl[4];          al[mt][3] = pl[8*CX_AP + 4];
            }
            uint32_t bhv[4][2], blv[4][2];
            #pragma unroll
            for (int nt = 0; nt < 4; nt++) {
                int nrow = wn * 32 + nt * 8 + gid;
                const uint32_t* pbh = BH + (kwb + ctid) * CX_BP + nrow;
                const uint32_t* pbl = BL + (kwb + ctid) * CX_BP + nrow;
                bhv[nt][0] = pbh[0]; bhv[nt][1] = pbh[4*CX_BP];
                blv[nt][0] = pbl[0]; blv[nt][1] = pbl[4*CX_BP];
            }
            MMA_PASSES(acc, ah, al, bhv, blv);
        }
    }

    #pragma unroll
    for (int mt = 0; mt < 2; mt++)
        #pragma unroll
        for (int nt = 0; nt < 4; nt++) {
            int row = m0 + wm * 32 + mt * 16 + gid;
            int col = wn * 32 + nt * 8 + 2 * ctid;
            float* op = g_ctx + ((size_t)b * SS + row) * EE + h * DD + col;
            *(float2*)op = make_float2(acc[mt][nt][0], acc[mt][nt][1]);
            *(float2*)(op + (size_t)8 * EE) = make_float2(acc[mt][nt][2], acc[mt][nt][3]);
        }
}

// =============================================================================
// Kernel 3: output projection (R13 mainloop; A staged by copy from fcw planes).
// =============================================================================
#define GF_AP 20
#define GF_AHo 0
#define GF_ALo 2560
#define GF_BHo 5120
#define GF_BLo 6400
#define GF_SMEM_WORDS 7680
#define GF_SMEM_BYTES (GF_SMEM_WORDS * 4)

__global__ __launch_bounds__(256) void fc_mma_kernel(
    const float* __restrict__ fcb, float* __restrict__ out)
{
    extern __shared__ uint32_t su[];
    uint32_t* AH = su + GF_AHo;
    uint32_t* AL = su + GF_ALo;
    uint32_t* BH = su + GF_BHo;
    uint32_t* BL = su + GF_BLo;

    const int b  = blockIdx.z;
    const int m0 = blockIdx.x * 128;
    const int n0 = blockIdx.y * 64;

    const float* ctx = g_ctx + (size_t)b * SS * EE;
    const uint32_t* awh = g_wh + (size_t)3 * EE * EW;
    const uint32_t* awl = g_wl + (size_t)3 * EE * EW;

    const int tid  = threadIdx.x;
    const int lane = tid & 31;
    const int w8   = tid >> 5;
    const int wm   = w8 >> 1;
    const int wn   = w8 & 1;
    const int gid  = lane >> 2;
    const int ctid = lane & 3;

    float acc[2][4][4];
    #pragma unroll
    for (int i = 0; i < 2; i++)
        #pragma unroll
        for (int j = 0; j < 4; j++)
            #pragma unroll
            for (int q = 0; q < 4; q++) acc[i][j][q] = 0.f;

    for (int kg = 0; kg < EE; kg += 32) {
        const int kg2 = kg >> 1;
        __syncthreads();
        // stage A: pure copy from fcw planes
        #pragma unroll
        for (int p = 0; p < 2; p++) {
            int idx = tid + p * 256;
            int r   = idx >> 2;
            int w4  = (idx & 3) << 2;
            size_t src = (size_t)(m0 + r) * EW + kg2 + w4;
            *(uint4*)(AH + r * GF_AP + w4) = *(const uint4*)(awh + src);
            *(uint4*)(AL + r * GF_AP + w4) = *(const uint4*)(awl + src);
        }
        // stage B (ctx fp32): split as R13
        {
            int r  = tid >> 2;
            int kq = (tid & 3) << 3;
            const float* br = ctx + (size_t)(n0 + r) * EE + kg + kq;
            float4 b0 = *(const float4*)br;
            float4 b1 = *(const float4*)(br + 4);
            uint4 hv, lv;
            split2_bf16(b0.x, b0.y, hv.x, lv.x);
            split2_bf16(b0.z, b0.w, hv.y, lv.y);
            split2_bf16(b1.x, b1.y, hv.z, lv.z);
            split2_bf16(b1.z, b1.w, hv.w, lv.w);
            *(uint4*)(BH + r * GF_AP + (tid & 3) * 4) = hv;
            *(uint4*)(BL + r * GF_AP + (tid & 3) * 4) = lv;
        }
        __syncthreads();

        #pragma unroll
        for (int kwb = 0; kwb < 16; kwb += 8) {
            uint32_t ah[2][4], al[2][4];
            #pragma unroll
            for (int mt = 0; mt < 2; mt++) {
                int mrow = wm * 32 + mt * 16 + gid;
                const uint32_t* ph = AH + mrow * GF_AP + kwb + ctid;
                const uint32_t* pl = AL + mrow * GF_AP + kwb + ctid;
                ah[mt][0] = ph[0];          ah[mt][1] = ph[8*GF_AP];
                ah[mt][2] = ph[4];          ah[mt][3] = ph[8*GF_AP + 4];
                al[mt][0] = pl[0];          al[mt][1] = pl[8*GF_AP];
                al[mt][2] = pl[4];          al[mt][3] = pl[8*GF_AP + 4];
            }
            uint32_t bhv[4][2], blv[4][2];
            #pragma unroll
            for (int nt = 0; nt < 4; nt++) {
                int nrow = wn * 32 + nt * 8 + gid;
                const uint32_t* pbh = BH + nrow * GF_AP + kwb + ctid;
                const uint32_t* pbl = BL + nrow * GF_AP + kwb + ctid;
                bhv[nt][0] = pbh[0]; bhv[nt][1] = pbh[4];
                blv[nt][0] = pbl[0]; blv[nt][1] = pbl[4];
            }
            MMA_PASSES(acc, ah, al, bhv, blv);
        }
    }

    #pragma unroll
    for (int mt = 0; mt < 2; mt++) {
        int row = m0 + wm * 32 + mt * 16 + gid;
        float fb0 = fcb[row];
        float fb1 = fcb[row + 8];
        #pragma unroll
        for (int nt = 0; nt < 4; nt++) {
            int col = n0 + wn * 32 + nt * 8 + 2 * ctid;
            *(float2*)(out + ((size_t)b * EE + row) * SS + col) =
                make_float2(acc[mt][nt][0] + fb0, acc[mt][nt][1] + fb0);
            *(float2*)(out + ((size_t)b * EE + row + 8) * SS + col) =
                make_float2(acc[mt][nt][2] + fb1, acc[mt][nt][3] + fb1);
        }
    }
}

// =============================================================================
extern "C" void kernel_launch(void* const* d_in, const int* in_sizes, int n_in,
                              void* d_out, int out_size)
{
    const float* q_img = (const float*)d_in[0];
    const float* k_img = (const float*)d_in[1];
    const float* v_img = (const float*)d_in[2];
    const float* wq_w  = (const float*)d_in[3];
    const float* wq_b  = (const float*)d_in[4];
    const float* wk_w  = (const float*)d_in[5];
    const float* wk_b  = (const float*)d_in[6];
    const float* wv_w  = (const float*)d_in[7];
    const float* wv_b  = (const float*)d_in[8];
    const float* fc_w  = (const float*)d_in[9];
    const float* fc_b  = (const float*)d_in[10];

    float* out   = (float*)d_out;
    float* probs = out + (size_t)BB * EE * SS;   // tuple output: (out, probs)

    cudaFuncSetAttribute(proj_mma_kernel, cudaFuncAttributeMaxDynamicSharedMemorySize,
                         GP_SMEM_BYTES);
    cudaFuncSetAttribute(scores_mma_kernel, cudaFuncAttributeMaxDynamicSharedMemorySize,
                         SK_SMEM_BYTES);
    cudaFuncSetAttribute(ctx_mma_kernel, cudaFuncAttributeMaxDynamicSharedMemorySize,
                         CX_SMEM_BYTES);
    cudaFuncSetAttribute(fc_mma_kernel, cudaFuncAttributeMaxDynamicSharedMemorySize,
                         GF_SMEM_BYTES);

    // 0) pre-split X and weights into bf16 hi/lo plane buffers (split once)
    presplit_x_kernel<<<(3 * BB * EW * SS) / 4 / 256, 256>>>(q_img, k_img, v_img);
    presplit_w_kernel<<<(4 * EE * EW) / 4 / 256, 256>>>(wq_w, wk_w, wv_w, fc_w);

    // 1) QKV projections (copy-staged)
    proj_mma_kernel<<<dim3(SS / 128, EE / 64, 3 * BB), 256, GP_SMEM_BYTES>>>(
        wq_b, wk_b, wv_b);

    // 2a) scores -> raw into probs buffer
    scores_mma_kernel<<<dim3(SS / 128, SS / 64, BB * NH), 256, SK_SMEM_BYTES>>>(probs);

    // 2b) in-place softmax over probs rows
    softmax_kernel<<<(BB * NH * SS) / 8, 256>>>(probs);

    // 2c) ctx = P @ V
    ctx_mma_kernel<<<dim3(SS / 128, 1, BB * NH), 256, CX_SMEM_BYTES>>>(probs);

    // 3) output projection (A copy-staged)
    fc_mma_kernel<<<dim3(EE / 128, SS / 64, BB), 256, GF_SMEM_BYTES>>>(fc_b, out);
}

// round 16
// speedup vs baseline: 1.0819x; 1.0819x over previous
#include <cuda_runtime.h>
#include <cuda_bf16.h>
#include <cstdint>

// Problem dims
#define BB 8
#define SS 1024          // IMG*IMG
#define EE 768           // D_EMBED == D_MODEL
#define NH 12
#define DD 64

// ---------------- scratch (device globals; no allocs allowed) ----------------
__device__ float g_q[BB * SS * EE];
__device__ float g_k[BB * SS * EE];
__device__ float g_v[BB * SS * EE];
__device__ float g_ctx[BB * SS * EE];

// =============================================================================
// bf16 split helpers: x = hi + lo, both bf16. Packed pairs along k.
// =============================================================================
__device__ __forceinline__ void split2_bf16(float x0, float x1,
                                            uint32_t& hw, uint32_t& lw) {
    __nv_bfloat162 h = __floats2bfloat162_rn(x0, x1);
    float2 hf = __bfloat1622float2(h);
    __nv_bfloat162 l = __floats2bfloat162_rn(x0 - hf.x, x1 - hf.y);
    hw = *reinterpret_cast<uint32_t*>(&h);
    lw = *reinterpret_cast<uint32_t*>(&l);
}

__device__ __forceinline__ void mma_bf16(float* d, const uint32_t* a, const uint32_t* b) {
    asm volatile(
        "mma.sync.aligned.m16n8k16.row.col.f32.bf16.bf16.f32 "
        "{%0,%1,%2,%3}, {%4,%5,%6,%7}, {%8,%9}, {%0,%1,%2,%3};"
        : "+f"(d[0]), "+f"(d[1]), "+f"(d[2]), "+f"(d[3])
        : "r"(a[0]), "r"(a[1]), "r"(a[2]), "r"(a[3]),
          "r"(b[0]), "r"(b[1]));
}

// Three interleaved passes over all 8 (mt,nt) accumulators: dependent mmas on
// the same accumulator are 8 instructions apart instead of back-to-back.
// Per-acc accumulation order (ahbh, ahbl, albh) is unchanged -> bitwise same.
#define MMA_PASSES(acc, ah, al, bhv, blv)                                   \
    do {                                                                    \
        _Pragma("unroll")                                                   \
        for (int nt_ = 0; nt_ < 4; nt_++) {                                 \
            _Pragma("unroll")                                               \
            for (int mt_ = 0; mt_ < 2; mt_++)                               \
                mma_bf16(acc[mt_][nt_], ah[mt_], bhv[nt_]);                 \
        }                                                                   \
        _Pragma("unroll")                                                   \
        for (int nt_ = 0; nt_ < 4; nt_++) {                                 \
            _Pragma("unroll")                                               \
            for (int mt_ = 0; mt_ < 2; mt_++)                               \
                mma_bf16(acc[mt_][nt_], ah[mt_], blv[nt_]);                 \
        }                                                                   \
        _Pragma("unroll")                                                   \
        for (int nt_ = 0; nt_ < 4; nt_++) {                                 \
            _Pragma("unroll")                                               \
            for (int mt_ = 0; mt_ < 2; mt_++)                               \
                mma_bf16(acc[mt_][nt_], al[mt_], bhv[nt_]);                 \
        }                                                                   \
    } while (0)

// =============================================================================
// Kernel 1: QKV projection (R13 layouts; interleaved mma passes).
// =============================================================================
#define GP_AP 136
#define GP_BP 20
#define GP_AHo 0
#define GP_ALo 2176
#define GP_BHo 4352
#define GP_BLo 5632
#define GP_SMEM_WORDS 6912
#define GP_SMEM_BYTES (GP_SMEM_WORDS * 4)

__global__ __launch_bounds__(256) void proj_mma_kernel(
    const float* __restrict__ xq, const float* __restrict__ xk, const float* __restrict__ xv,
    const float* __restrict__ wq, const float* __restrict__ wk, const float* __restrict__ wv,
    const float* __restrict__ bq, const float* __restrict__ bk, const float* __restrict__ bv)
{
    extern __shared__ uint32_t su[];
    uint32_t* AH = su + GP_AHo;
    uint32_t* AL = su + GP_ALo;
    uint32_t* BH = su + GP_BHo;
    uint32_t* BL = su + GP_BLo;

    const int mat = blockIdx.z >> 3;
    const int b   = blockIdx.z & 7;

    const float* x; const float* w; const float* bi; float* y;
    if (mat == 0)      { x = xq; w = wq; bi = bq; y = g_q; }
    else if (mat == 1) { x = xk; w = wk; bi = bk; y = g_k; }
    else               { x = xv; w = wv; bi = bv; y = g_v; }
    x += (size_t)b * EE * SS;
    y += (size_t)b * SS * EE;

    const int m0 = blockIdx.x * 128;
    const int n0 = blockIdx.y * 64;

    const int tid  = threadIdx.x;
    const int lane = tid & 31;
    const int w8   = tid >> 5;
    const int wm   = w8 >> 1;
    const int wn   = w8 & 1;
    const int gid  = lane >> 2;
    const int ctid = lane & 3;

    float acc[2][4][4];
    #pragma unroll
    for (int i = 0; i < 2; i++)
        #pragma unroll
        for (int j = 0; j < 4; j++)
            #pragma unroll
            for (int q = 0; q < 4; q++) acc[i][j][q] = 0.f;

    for (int kg = 0; kg < EE; kg += 32) {
        __syncthreads();
        #pragma unroll
        for (int p = 0; p < 2; p++) {
            int idx = tid + p * 256;
            int j   = idx >> 5;
            int m4  = (idx & 31) << 2;
            const float* xr = x + (size_t)(kg + 2 * j) * SS + m0 + m4;
            float4 ra = *(const float4*)xr;
            float4 rb = *(const float4*)(xr + SS);
            uint4 hv, lv;
            split2_bf16(ra.x, rb.x, hv.x, lv.x);
            split2_bf16(ra.y, rb.y, hv.y, lv.y);
            split2_bf16(ra.z, rb.z, hv.z, lv.z);
            split2_bf16(ra.w, rb.w, hv.w, lv.w);
            *(uint4*)(AH + j * GP_AP + m4) = hv;
            *(uint4*)(AL + j * GP_AP + m4) = lv;
        }
        {
            int r  = tid >> 2;
            int kq = (tid & 3) << 3;
            const float* wr = w + (size_t)(n0 + r) * EE + kg + kq;
            float4 b0 = *(const float4*)wr;
            float4 b1 = *(const float4*)(wr + 4);
            uint4 hv, lv;
            split2_bf16(b0.x, b0.y, hv.x, lv.x);
            split2_bf16(b0.z, b0.w, hv.y, lv.y);
            split2_bf16(b1.x, b1.y, hv.z, lv.z);
            split2_bf16(b1.z, b1.w, hv.w, lv.w);
            *(uint4*)(BH + r * GP_BP + (tid & 3) * 4) = hv;
            *(uint4*)(BL + r * GP_BP + (tid & 3) * 4) = lv;
        }
        __syncthreads();

        #pragma unroll
        for (int kwb = 0; kwb < 16; kwb += 8) {
            uint32_t ah[2][4], al[2][4];
            #pragma unroll
            for (int mt = 0; mt < 2; mt++) {
                int mrow = wm * 32 + mt * 16 + gid;
                const uint32_t* ph = AH + (kwb + ctid) * GP_AP + mrow;
                const uint32_t* pl = AL + (kwb + ctid) * GP_AP + mrow;
                ah[mt][0] = ph[0];          ah[mt][1] = ph[8];
                ah[mt][2] = ph[4*GP_AP];    ah[mt][3] = ph[4*GP_AP + 8];
                al[mt][0] = pl[0];          al[mt][1] = pl[8];
                al[mt][2] = pl[4*GP_AP];    al[mt][3] = pl[4*GP_AP + 8];
            }
            uint32_t bhv[4][2], blv[4][2];
            #pragma unroll
            for (int nt = 0; nt < 4; nt++) {
                int nrow = wn * 32 + nt * 8 + gid;
                const uint32_t* pbh = BH + nrow * GP_BP + kwb + ctid;
                const uint32_t* pbl = BL + nrow * GP_BP + kwb + ctid;
                bhv[nt][0] = pbh[0]; bhv[nt][1] = pbh[4];
                blv[nt][0] = pbl[0]; blv[nt][1] = pbl[4];
            }
            MMA_PASSES(acc, ah, al, bhv, blv);
        }
    }

    #pragma unroll
    for (int nt = 0; nt < 4; nt++) {
        int col = n0 + wn * 32 + nt * 8 + 2 * ctid;
        float b0 = bi[col], b1 = bi[col + 1];
        #pragma unroll
        for (int mt = 0; mt < 2; mt++) {
            int row = m0 + wm * 32 + mt * 16 + gid;
            *(float2*)(y + (size_t)row * EE + col) =
                make_float2(acc[mt][nt][0] + b0, acc[mt][nt][1] + b1);
            *(float2*)(y + (size_t)(row + 8) * EE + col) =
                make_float2(acc[mt][nt][2] + b0, acc[mt][nt][3] + b1);
        }
    }
}

// =============================================================================
// Kernel 2a: scores GEMM (R13 layouts; interleaved mma passes).
// =============================================================================
#define SK_P 36
#define SK_AHo 0
#define SK_ALo 4608
#define SK_BHo 9216
#define SK_BLo 11520
#define SK_SMEM_WORDS 13824
#define SK_SMEM_BYTES (SK_SMEM_WORDS * 4)

__global__ __launch_bounds__(256) void scores_mma_kernel(float* __restrict__ probs)
{
    extern __shared__ uint32_t su[];
    uint32_t* AH = su + SK_AHo;
    uint32_t* AL = su + SK_ALo;
    uint32_t* BH = su + SK_BHo;
    uint32_t* BL = su + SK_BLo;

    const int bh = blockIdx.z;
    const int b  = bh / NH;
    const int h  = bh % NH;
    const int m0 = blockIdx.x * 128;
    const int n0 = blockIdx.y * 64;

    const float* qp = g_q + ((size_t)b * SS) * EE + h * DD;
    const float* kp = g_k + ((size_t)b * SS) * EE + h * DD;

    const int tid  = threadIdx.x;
    const int lane = tid & 31;
    const int w8   = tid >> 5;
    const int wm   = w8 >> 1;
    const int wn   = w8 & 1;
    const int gid  = lane >> 2;
    const int ctid = lane & 3;

    #pragma unroll
    for (int p = 0; p < 4; p++) {
        int idx = tid + p * 256;
        int r   = idx >> 3;
        int kq  = (idx & 7) << 3;
        const float* qr = qp + (size_t)(m0 + r) * EE + kq;
        float4 a0 = *(const float4*)qr;
        float4 a1 = *(const float4*)(qr + 4);
        uint4 hv, lv;
        split2_bf16(a0.x, a0.y, hv.x, lv.x);
        split2_bf16(a0.z, a0.w, hv.y, lv.y);
        split2_bf16(a1.x, a1.y, hv.z, lv.z);
        split2_bf16(a1.z, a1.w, hv.w, lv.w);
        *(uint4*)(AH + r * SK_P + (idx & 7) * 4) = hv;
        *(uint4*)(AL + r * SK_P + (idx & 7) * 4) = lv;
    }
    #pragma unroll
    for (int p = 0; p < 2; p++) {
        int idx = tid + p * 256;
        int r   = idx >> 3;
        int kq  = (idx & 7) << 3;
        const float* kr = kp + (size_t)(n0 + r) * EE + kq;
        float4 b0 = *(const float4*)kr;
        float4 b1 = *(const float4*)(kr + 4);
        uint4 hv, lv;
        split2_bf16(b0.x, b0.y, hv.x, lv.x);
        split2_bf16(b0.z, b0.w, hv.y, lv.y);
        split2_bf16(b1.x, b1.y, hv.z, lv.z);
        split2_bf16(b1.z, b1.w, hv.w, lv.w);
        *(uint4*)(BH + r * SK_P + (idx & 7) * 4) = hv;
        *(uint4*)(BL + r * SK_P + (idx & 7) * 4) = lv;
    }
    __syncthreads();

    float acc[2][4][4];
    #pragma unroll
    for (int i = 0; i < 2; i++)
        #pragma unroll
        for (int j = 0; j < 4; j++)
            #pragma unroll
            for (int q = 0; q < 4; q++) acc[i][j][q] = 0.f;

    #pragma unroll
    for (int kwb = 0; kwb < 32; kwb += 8) {
        uint32_t ah[2][4], al[2][4];
        #pragma unroll
        for (int mt = 0; mt < 2; mt++) {
            int mrow = wm * 32 + mt * 16 + gid;
            const uint32_t* ph = AH + mrow * SK_P + kwb + ctid;
            const uint32_t* pl = AL + mrow * SK_P + kwb + ctid;
            ah[mt][0] = ph[0];          ah[mt][1] = ph[8*SK_P];
            ah[mt][2] = ph[4];          ah[mt][3] = ph[8*SK_P + 4];
            al[mt][0] = pl[0];          al[mt][1] = pl[8*SK_P];
            al[mt][2] = pl[4];          al[mt][3] = pl[8*SK_P + 4];
        }
        uint32_t bhv[4][2], blv[4][2];
        #pragma unroll
        for (int nt = 0; nt < 4; nt++) {
            int nrow = wn * 32 + nt * 8 + gid;
            const uint32_t* pbh = BH + nrow * SK_P + kwb + ctid;
            const uint32_t* pbl = BL + nrow * SK_P + kwb + ctid;
            bhv[nt][0] = pbh[0]; bhv[nt][1] = pbh[4];
            blv[nt][0] = pbl[0]; blv[nt][1] = pbl[4];
        }
        MMA_PASSES(acc, ah, al, bhv, blv);
    }

    float* pbase = probs + (size_t)bh * SS * SS;
    #pragma unroll
    for (int mt = 0; mt < 2; mt++)
        #pragma unroll
        for (int nt = 0; nt < 4; nt++) {
            int row = m0 + wm * 32 + mt * 16 + gid;
            int col = n0 + wn * 32 + nt * 8 + 2 * ctid;
            *(float2*)(pbase + (size_t)row * SS + col) =
                make_float2(acc[mt][nt][0] * 0.125f, acc[mt][nt][1] * 0.125f);
            *(float2*)(pbase + (size_t)(row + 8) * SS + col) =
                make_float2(acc[mt][nt][2] * 0.125f, acc[mt][nt][3] * 0.125f);
        }
}

// =============================================================================
// Kernel 2b: in-place row softmax (R13, unchanged; HBM-bound at roof).
// =============================================================================
__global__ __launch_bounds__(256) void softmax_kernel(float* __restrict__ probs)
{
    const int warp = threadIdx.x >> 5;
    const int lane = threadIdx.x & 31;
    const size_t row = (size_t)blockIdx.x * 8 + warp;

    float4* rp = (float4*)(probs + row * SS);

    float4 v[8];
    #pragma unroll
    for (int i = 0; i < 8; i++) v[i] = rp[lane + 32 * i];

    float mx = -3.4e38f;
    #pragma unroll
    for (int i = 0; i < 8; i++)
        mx = fmaxf(mx, fmaxf(fmaxf(v[i].x, v[i].y), fmaxf(v[i].z, v[i].w)));
    #pragma unroll
    for (int o = 16; o > 0; o >>= 1)
        mx = fmaxf(mx, __shfl_xor_sync(0xFFFFFFFFu, mx, o));

    float sum = 0.f;
    #pragma unroll
    for (int i = 0; i < 8; i++) {
        v[i].x = __expf(v[i].x - mx);
        v[i].y = __expf(v[i].y - mx);
        v[i].z = __expf(v[i].z - mx);
        v[i].w = __expf(v[i].w - mx);
        sum += v[i].x + v[i].y + v[i].z + v[i].w;
    }
    #pragma unroll
    for (int o = 16; o > 0; o >>= 1)
        sum += __shfl_xor_sync(0xFFFFFFFFu, sum, o);

    float inv = 1.f / sum;
    #pragma unroll
    for (int i = 0; i < 8; i++) {
        v[i].x *= inv; v[i].y *= inv; v[i].z *= inv; v[i].w *= inv;
        rp[lane + 32 * i] = v[i];
    }
}

// =============================================================================
// Kernel 2c: ctx GEMM (R13 layouts; interleaved mma passes).
// =============================================================================
#define CX_AP 20
#define CX_BP 72
#define CX_AHo 0
#define CX_ALo 2560
#define CX_BHo 5120
#define CX_BLo 6272
#define CX_SMEM_WORDS 7424
#define CX_SMEM_BYTES (CX_SMEM_WORDS * 4)

__global__ __launch_bounds__(256) void ctx_mma_kernel(const float* __restrict__ probs)
{
    extern __shared__ uint32_t su[];
    uint32_t* AH = su + CX_AHo;
    uint32_t* AL = su + CX_ALo;
    uint32_t* BH = su + CX_BHo;
    uint32_t* BL = su + CX_BLo;

    const int bh = blockIdx.z;
    const int b  = bh / NH;
    const int h  = bh % NH;
    const int m0 = blockIdx.x * 128;

    const float* pb = probs + (size_t)bh * SS * SS;
    const float* vb = g_v + ((size_t)b * SS) * EE + h * DD;

    const int tid  = threadIdx.x;
    const int lane = tid & 31;
    const int w8   = tid >> 5;
    const int wm   = w8 >> 1;
    const int wn   = w8 & 1;
    const int gid  = lane >> 2;
    const int ctid = lane & 3;

    float acc[2][4][4];
    #pragma unroll
    for (int i = 0; i < 2; i++)
        #pragma unroll
        for (int j = 0; j < 4; j++)
            #pragma unroll
            for (int q = 0; q < 4; q++) acc[i][j][q] = 0.f;

    for (int kg = 0; kg < SS; kg += 32) {
        __syncthreads();
        #pragma unroll
        for (int p = 0; p < 2; p++) {
            int idx = tid + p * 256;
            int r   = idx >> 2;
            int kq  = (idx & 3) << 3;
            const float* pr = pb + (size_t)(m0 + r) * SS + kg + kq;
            float4 a0 = *(const float4*)pr;
            float4 a1 = *(const float4*)(pr + 4);
            uint4 hv, lv;
            split2_bf16(a0.x, a0.y, hv.x, lv.x);
            split2_bf16(a0.z, a0.w, hv.y, lv.y);
            split2_bf16(a1.x, a1.y, hv.z, lv.z);
            split2_bf16(a1.z, a1.w, hv.w, lv.w);
            *(uint4*)(AH + r * CX_AP + (idx & 3) * 4) = hv;
            *(uint4*)(AL + r * CX_AP + (idx & 3) * 4) = lv;
        }
        {
            int j  = tid >> 4;
            int d4 = (tid & 15) << 2;
            const float* vr = vb + (size_t)(kg + 2 * j) * EE + d4;
            float4 r0 = *(const float4*)vr;
            float4 r1 = *(const float4*)(vr + EE);
            uint4 hv, lv;
            split2_bf16(r0.x, r1.x, hv.x, lv.x);
            split2_bf16(r0.y, r1.y, hv.y, lv.y);
            split2_bf16(r0.z, r1.z, hv.z, lv.z);
            split2_bf16(r0.w, r1.w, hv.w, lv.w);
            *(uint4*)(BH + j * CX_BP + d4) = hv;
            *(uint4*)(BL + j * CX_BP + d4) = lv;
        }
        __syncthreads();

        #pragma unroll
        for (int kwb = 0; kwb < 16; kwb += 8) {
            uint32_t ah[2][4], al[2][4];
            #pragma unroll
            for (int mt = 0; mt < 2; mt++) {
                int mrow = wm * 32 + mt * 16 + gid;
                const uint32_t* ph = AH + mrow * CX_AP + kwb + ctid;
                const uint32_t* pl = AL + mrow * CX_AP + kwb + ctid;
                ah[mt][0] = ph[0];          ah[mt][1] = ph[8*CX_AP];
                ah[mt][2] = ph[4];          ah[mt][3] = ph[8*CX_AP + 4];
                al[mt][0] = pl[0];          al[mt][1] = pl[8*CX_AP];
                al[mt][2] = pl[4];          al[mt][3] = pl[8*CX_AP + 4];
            }
            uint32_t bhv[4][2], blv[4][2];
            #pragma unroll
            for (int nt = 0; nt < 4; nt++) {
                int nrow = wn * 32 + nt * 8 + gid;
                const uint32_t* pbh = BH + (kwb + ctid) * CX_BP + nrow;
                const uint32_t* pbl = BL + (kwb + ctid) * CX_BP + nrow;
                bhv[nt][0] = pbh[0]; bhv[nt][1] = pbh[4*CX_BP];
                blv[nt][0] = pbl[0]; blv[nt][1] = pbl[4*CX_BP];
            }
            MMA_PASSES(acc, ah, al, bhv, blv);
        }
    }

    #pragma unroll
    for (int mt = 0; mt < 2; mt++)
        #pragma unroll
        for (int nt = 0; nt < 4; nt++) {
            int row = m0 + wm * 32 + mt * 16 + gid;
            int col = wn * 32 + nt * 8 + 2 * ctid;
            float* op = g_ctx + ((size_t)b * SS + row) * EE + h * DD + col;
            *(float2*)op = make_float2(acc[mt][nt][0], acc[mt][nt][1]);
            *(float2*)(op + (size_t)8 * EE) = make_float2(acc[mt][nt][2], acc[mt][nt][3]);
        }
}

// =============================================================================
// Kernel 3: output projection (R13 layouts; interleaved mma passes).
// =============================================================================
#define GF_AP 20
#define GF_AHo 0
#define GF_ALo 2560
#define GF_BHo 5120
#define GF_BLo 6400
#define GF_SMEM_WORDS 7680
#define GF_SMEM_BYTES (GF_SMEM_WORDS * 4)

__global__ __launch_bounds__(256) void fc_mma_kernel(
    const float* __restrict__ fcw, const float* __restrict__ fcb,
    float* __restrict__ out)
{
    extern __shared__ uint32_t su[];
    uint32_t* AH = su + GF_AHo;
    uint32_t* AL = su + GF_ALo;
    uint32_t* BH = su + GF_BHo;
    uint32_t* BL = su + GF_BLo;

    const int b  = blockIdx.z;
    const int m0 = blockIdx.x * 128;
    const int n0 = blockIdx.y * 64;

    const float* ctx = g_ctx + (size_t)b * SS * EE;

    const int tid  = threadIdx.x;
    const int lane = tid & 31;
    const int w8   = tid >> 5;
    const int wm   = w8 >> 1;
    const int wn   = w8 & 1;
    const int gid  = lane >> 2;
    const int ctid = lane & 3;

    float acc[2][4][4];
    #pragma unroll
    for (int i = 0; i < 2; i++)
        #pragma unroll
        for (int j = 0; j < 4; j++)
            #pragma unroll
            for (int q = 0; q < 4; q++) acc[i][j][q] = 0.f;

    for (int kg = 0; kg < EE; kg += 32) {
        __syncthreads();
        #pragma unroll
        for (int p = 0; p < 2; p++) {
            int idx = tid + p * 256;
            int r   = idx >> 2;
            int kq  = (idx & 3) << 3;
            const float* ar = fcw + (size_t)(m0 + r) * EE + kg + kq;
            float4 a0 = *(const float4*)ar;
            float4 a1 = *(const float4*)(ar + 4);
            uint4 hv, lv;
            split2_bf16(a0.x, a0.y, hv.x, lv.x);
            split2_bf16(a0.z, a0.w, hv.y, lv.y);
            split2_bf16(a1.x, a1.y, hv.z, lv.z);
            split2_bf16(a1.z, a1.w, hv.w, lv.w);
            *(uint4*)(AH + r * GF_AP + (idx & 3) * 4) = hv;
            *(uint4*)(AL + r * GF_AP + (idx & 3) * 4) = lv;
        }
        {
            int r  = tid >> 2;
            int kq = (tid & 3) << 3;
            const float* br = ctx + (size_t)(n0 + r) * EE + kg + kq;
            float4 b0 = *(const float4*)br;
            float4 b1 = *(const float4*)(br + 4);
            uint4 hv, lv;
            split2_bf16(b0.x, b0.y, hv.x, lv.x);
            split2_bf16(b0.z, b0.w, hv.y, lv.y);
            split2_bf16(b1.x, b1.y, hv.z, lv.z);
            split2_bf16(b1.z, b1.w, hv.w, lv.w);
            *(uint4*)(BH + r * GF_AP + (tid & 3) * 4) = hv;
            *(uint4*)(BL + r * GF_AP + (tid & 3) * 4) = lv;
        }
        __syncthreads();

        #pragma unroll
        for (int kwb = 0; kwb < 16; kwb += 8) {
            uint32_t ah[2][4], al[2][4];
            #pragma unroll
            for (int mt = 0; mt < 2; mt++) {
                int mrow = wm * 32 + mt * 16 + gid;
                const uint32_t* ph = AH + mrow * GF_AP + kwb + ctid;
                const uint32_t* pl = AL + mrow * GF_AP + kwb + ctid;
                ah[mt][0] = ph[0];          ah[mt][1] = ph[8*GF_AP];
                ah[mt][2] = ph[4];          ah[mt][3] = ph[8*GF_AP + 4];
                al[mt][0] = pl[0];          al[mt][1] = pl[8*GF_AP];
                al[mt][2] = pl[4];          al[mt][3] = pl[8*GF_AP + 4];
            }
            uint32_t bhv[4][2], blv[4][2];
            #pragma unroll
            for (int nt = 0; nt < 4; nt++) {
                int nrow = wn * 32 + nt * 8 + gid;
                const uint32_t* pbh = BH + nrow * GF_AP + kwb + ctid;
                const uint32_t* pbl = BL + nrow * GF_AP + kwb + ctid;
                bhv[nt][0] = pbh[0]; bhv[nt][1] = pbh[4];
                blv[nt][0] = pbl[0]; blv[nt][1] = pbl[4];
            }
            MMA_PASSES(acc, ah, al, bhv, blv);
        }
    }

    #pragma unroll
    for (int mt = 0; mt < 2; mt++) {
        int row = m0 + wm * 32 + mt * 16 + gid;
        float fb0 = fcb[row];
        float fb1 = fcb[row + 8];
        #pragma unroll
        for (int nt = 0; nt < 4; nt++) {
            int col = n0 + wn * 32 + nt * 8 + 2 * ctid;
            *(float2*)(out + ((size_t)b * EE + row) * SS + col) =
                make_float2(acc[mt][nt][0] + fb0, acc[mt][nt][1] + fb0);
            *(float2*)(out + ((size_t)b * EE + row + 8) * SS + col) =
                make_float2(acc[mt][nt][2] + fb1, acc[mt][nt][3] + fb1);
        }
    }
}

// =============================================================================
extern "C" void kernel_launch(void* const* d_in, const int* in_sizes, int n_in,
                              void* d_out, int out_size)
{
    const float* q_img = (const float*)d_in[0];
    const float* k_img = (const float*)d_in[1];
    const float* v_img = (const float*)d_in[2];
    const float* wq_w  = (const float*)d_in[3];
    const float* wq_b  = (const float*)d_in[4];
    const float* wk_w  = (const float*)d_in[5];
    const float* wk_b  = (const float*)d_in[6];
    const float* wv_w  = (const float*)d_in[7];
    const float* wv_b  = (const float*)d_in[8];
    const float* fc_w  = (const float*)d_in[9];
    const float* fc_b  = (const float*)d_in[10];

    float* out   = (float*)d_out;
    float* probs = out + (size_t)BB * EE * SS;   // tuple output: (out, probs)

    cudaFuncSetAttribute(proj_mma_kernel, cudaFuncAttributeMaxDynamicSharedMemorySize,
                         GP_SMEM_BYTES);
    cudaFuncSetAttribute(scores_mma_kernel, cudaFuncAttributeMaxDynamicSharedMemorySize,
                         SK_SMEM_BYTES);
    cudaFuncSetAttribute(ctx_mma_kernel, cudaFuncAttributeMaxDynamicSharedMemorySize,
                         CX_SMEM_BYTES);
    cudaFuncSetAttribute(fc_mma_kernel, cudaFuncAttributeMaxDynamicSharedMemorySize,
                         GF_SMEM_BYTES);

    // 1) QKV projections
    proj_mma_kernel<<<dim3(SS / 128, EE / 64, 3 * BB), 256, GP_SMEM_BYTES>>>(
        q_img, k_img, v_img, wq_w, wk_w, wv_w, wq_b, wk_b, wv_b);

    // 2a) scores -> raw into probs buffer
    scores_mma_kernel<<<dim3(SS / 128, SS / 64, BB * NH), 256, SK_SMEM_BYTES>>>(probs);

    // 2b) in-place softmax over probs rows
    softmax_kernel<<<(BB * NH * SS) / 8, 256>>>(probs);

    // 2c) ctx = P @ V
    ctx_mma_kernel<<<dim3(SS / 128, 1, BB * NH), 256, CX_SMEM_BYTES>>>(probs);

    // 3) output projection
    fc_mma_kernel<<<dim3(EE / 128, SS / 64, BB), 256, GF_SMEM_BYTES>>>(fc_w, fc_b, out);
}